// round 5
// baseline (speedup 1.0000x reference)
#include <cuda_runtime.h>
#include <cuda_bf16.h>
#include <math.h>
#include <stdint.h>

// Problem constants
#define NTOK 2048
#define CDIM 768
#define EDIM 8
#define HDIM 3072
#define CAP  2048

// ---------------- scratch (static device memory; no allocations) ----------------
__device__ float g_xbuf[(size_t)EDIM * CAP * CDIM];   // gathered activations (tf32 RNA-rounded)
__device__ float g_u   [(size_t)EDIM * CAP * HDIM];   // h*silu(g) (tf32 RNA-rounded)
__device__ float g_o   [(size_t)EDIM * CAP * CDIM];   // proj out split 0
__device__ float g_o2  [(size_t)EDIM * CAP * CDIM];   // proj out split 1
__device__ int   g_cnt [EDIM];
__device__ float g_prob[EDIM * CAP];
__device__ int   g_pidx[2 * NTOK];

// ---------------- helpers ----------------
__device__ __forceinline__ float to_tf32(float x) {
    unsigned u;
    asm("cvt.rna.tf32.f32 %0, %1;" : "=r"(u) : "f"(x));
    return __uint_as_float(u);
}

__device__ __forceinline__ unsigned lds_tf32(const float* p) {
    return __float_as_uint(to_tf32(*p));
}

__device__ __forceinline__ void mma_tf32(float c[4], const unsigned a[4], const unsigned b[2]) {
    asm volatile(
        "mma.sync.aligned.m16n8k8.row.col.f32.tf32.tf32.f32 "
        "{%0,%1,%2,%3},{%4,%5,%6,%7},{%8,%9},{%0,%1,%2,%3};\n"
        : "+f"(c[0]), "+f"(c[1]), "+f"(c[2]), "+f"(c[3])
        : "r"(a[0]), "r"(a[1]), "r"(a[2]), "r"(a[3]), "r"(b[0]), "r"(b[1]));
}

__device__ __forceinline__ void cpa16(uint32_t dst, const void* src, int sz) {
    asm volatile("cp.async.cg.shared.global [%0], [%1], 16, %2;"
                 :: "r"(dst), "l"(src), "r"(sz));
}
__device__ __forceinline__ void cpa16u(uint32_t dst, const void* src) {
    asm volatile("cp.async.cg.shared.global [%0], [%1], 16;"
                 :: "r"(dst), "l"(src));
}
__device__ __forceinline__ void cpa_commit() { asm volatile("cp.async.commit_group;"); }
__device__ __forceinline__ void cpa_wait1()  { asm volatile("cp.async.wait_group 1;" ::: "memory"); }
__device__ __forceinline__ void cpa_wait0()  { asm volatile("cp.async.wait_group 0;" ::: "memory"); }

__device__ __forceinline__ uint32_t smem_u32(const void* p) {
    return (uint32_t)__cvta_generic_to_shared(p);
}

// ---------------- kernel 0: init counters ----------------
__global__ void init_kernel() {
    if (threadIdx.x < EDIM) g_cnt[threadIdx.x] = 0;
}

// ---------------- kernel 1: router + dispatch/gather (tf32 RNA-rounded gather) ----------------
__global__ __launch_bounds__(256) void router_kernel(const float* __restrict__ x,
                                                     const float* __restrict__ wr) {
    const int t = blockIdx.x * 8 + (threadIdx.x >> 5);
    if (t >= NTOK) return;
    const int lane = threadIdx.x & 31;
    const float* xr = x + (size_t)t * CDIM;

    float acc[EDIM];
#pragma unroll
    for (int e = 0; e < EDIM; e++) acc[e] = 0.f;
#pragma unroll
    for (int j = 0; j < CDIM / 32; j++) {
        int i = lane + 32 * j;
        float xv = xr[i];
        const float4* w4 = reinterpret_cast<const float4*>(wr + (size_t)i * EDIM);
        float4 w0 = w4[0], w1 = w4[1];
        acc[0] += xv * w0.x; acc[1] += xv * w0.y; acc[2] += xv * w0.z; acc[3] += xv * w0.w;
        acc[4] += xv * w1.x; acc[5] += xv * w1.y; acc[6] += xv * w1.z; acc[7] += xv * w1.w;
    }
#pragma unroll
    for (int off = 16; off > 0; off >>= 1) {
#pragma unroll
        for (int e = 0; e < EDIM; e++) acc[e] += __shfl_xor_sync(0xffffffffu, acc[e], off);
    }
    int e0 = 0; float l0 = acc[0];
#pragma unroll
    for (int e = 1; e < EDIM; e++) if (acc[e] > l0) { l0 = acc[e]; e0 = e; }
    int e1 = -1; float l1 = -INFINITY;
#pragma unroll
    for (int e = 0; e < EDIM; e++) if (e != e0 && acc[e] > l1) { l1 = acc[e]; e1 = e; }

    float ex = expf(l1 - l0);
    float p0 = 1.f / (1.f + ex);
    float p1 = ex * p0;

    int s0 = 0, s1 = 0;
    if (lane == 0) {
        s0 = atomicAdd(&g_cnt[e0], 1);
        s1 = atomicAdd(&g_cnt[e1], 1);
        g_prob[e0 * CAP + s0] = p0;
        g_prob[e1 * CAP + s1] = p1;
        g_pidx[2 * t + 0] = e0 * CAP + s0;
        g_pidx[2 * t + 1] = e1 * CAP + s1;
    }
    s0 = __shfl_sync(0xffffffffu, s0, 0);
    s1 = __shfl_sync(0xffffffffu, s1, 0);

    float* d0 = g_xbuf + ((size_t)e0 * CAP + s0) * CDIM;
    float* d1 = g_xbuf + ((size_t)e1 * CAP + s1) * CDIM;
#pragma unroll
    for (int j = 0; j < CDIM / 32; j++) {
        int i = lane + 32 * j;
        float v = to_tf32(xr[i]);
        d0[i] = v;
        d1[i] = v;
    }
}

// ================= GEMM1: fused fc+gate, block 128x64 (x2), BK=32, cp.async 3-stage =================
// smem (floats) per stage: A 128*36 | Bf 32*72 | Bg 32*72 = 9216 floats = 36864 B; 3 stages = 110592 B
#define G1_AS    4608
#define G1_BS    2304
#define G1_STG   (G1_AS + 2 * G1_BS)      // floats per stage
#define G1_SMEM_BYTES (3 * G1_STG * 4)

__global__ __launch_bounds__(256, 2) void gemm1_kernel(const float* __restrict__ wfc,
                                                       const float* __restrict__ bfc,
                                                       const float* __restrict__ wgt,
                                                       const float* __restrict__ bgt) {
    extern __shared__ float smem[];
    const int e   = blockIdx.z;
    const int cnt = g_cnt[e];
    const int m0  = blockIdx.y * 128;
    if (m0 >= cnt) return;
    const int n0  = blockIdx.x * 64;

    const float* Ag = g_xbuf + (size_t)e * CAP * CDIM;
    const float* B0 = wfc + (size_t)e * CDIM * HDIM;
    const float* B1 = wgt + (size_t)e * CDIM * HDIM;

    const int tid = threadIdx.x, lane = tid & 31, wid = tid >> 5;
    const int wm = (wid & 3) * 32, wn = (wid >> 2) * 32;
    const int gq = lane >> 2, tg = lane & 3;

    const uint32_t sBase = smem_u32(smem);

    // per-stage layout: [A: 128*36][Bf: 32*72][Bg: 32*72]
    auto load_stage = [&](int buf, int k0) {
        const uint32_t sA  = sBase + (uint32_t)(buf * G1_STG) * 4;
        const uint32_t sBf = sA + G1_AS * 4;
        const uint32_t sBg = sBf + G1_BS * 4;
#pragma unroll
        for (int i = 0; i < 4; i++) {
            int v = tid + 256 * i, row = v >> 3, c4 = v & 7;
            int sz = (m0 + row < cnt) ? 16 : 0;
            cpa16(sA + (uint32_t)(row * 36 + c4 * 4) * 4,
                  Ag + (size_t)(m0 + row) * CDIM + k0 + c4 * 4, sz);
        }
#pragma unroll
        for (int i = 0; i < 2; i++) {
            int v = tid + 256 * i, row = v >> 4, c4 = v & 15;
            size_t off = (size_t)(k0 + row) * HDIM + n0 + c4 * 4;
            uint32_t so = (uint32_t)(row * 72 + c4 * 4) * 4;
            cpa16u(sBf + so, B0 + off);
            cpa16u(sBg + so, B1 + off);
        }
        cpa_commit();
    };

    float cf[2][4][4] = {};
    float cg[2][4][4] = {};

    const int NIT = CDIM / 32;  // 24
    load_stage(0, 0);
    load_stage(1, 32);

#pragma unroll 1
    for (int it = 0; it < NIT; ++it) {
        if (it + 1 < NIT) cpa_wait1(); else cpa_wait0();
        __syncthreads();
        // safe: buffer (it+2)%3 held stage it-1, whose compute finished before this barrier
        if (it + 2 < NIT) load_stage((it + 2) % 3, (it + 2) * 32);

        const int cur = it % 3;
        const float* As = smem + cur * G1_STG;
        const float* Bf = As + G1_AS;
        const float* Bg = Bf + G1_BS;
#pragma unroll
        for (int ks = 0; ks < 4; ks++) {
            const int kb = ks * 8;
            unsigned af[2][4];
#pragma unroll
            for (int mt = 0; mt < 2; mt++) {
                int r = wm + mt * 16 + gq;
                af[mt][0] = __float_as_uint(As[r * 36 + kb + tg]);
                af[mt][1] = __float_as_uint(As[(r + 8) * 36 + kb + tg]);
                af[mt][2] = __float_as_uint(As[r * 36 + kb + tg + 4]);
                af[mt][3] = __float_as_uint(As[(r + 8) * 36 + kb + tg + 4]);
            }
            unsigned bF[4][2], bG[4][2];
#pragma unroll
            for (int nt = 0; nt < 4; nt++) {
                int cc = wn + nt * 8 + gq;
                bF[nt][0] = lds_tf32(&Bf[(kb + tg) * 72 + cc]);
                bF[nt][1] = lds_tf32(&Bf[(kb + tg + 4) * 72 + cc]);
                bG[nt][0] = lds_tf32(&Bg[(kb + tg) * 72 + cc]);
                bG[nt][1] = lds_tf32(&Bg[(kb + tg + 4) * 72 + cc]);
            }
#pragma unroll
            for (int mt = 0; mt < 2; mt++)
#pragma unroll
                for (int nt = 0; nt < 4; nt++) {
                    mma_tf32(cf[mt][nt], af[mt], bF[nt]);
                    mma_tf32(cg[mt][nt], af[mt], bG[nt]);
                }
        }
    }

    // epilogue: u = (h+bfc) * silu(g+bg), RNA tf32-rounded
    float* U = g_u + (size_t)e * CAP * HDIM;
#pragma unroll
    for (int mt = 0; mt < 2; mt++) {
#pragma unroll
        for (int nt = 0; nt < 4; nt++) {
            int col = n0 + wn + nt * 8 + tg * 2;
            float bf0 = bfc[(size_t)e * HDIM + col], bf1 = bfc[(size_t)e * HDIM + col + 1];
            float bg0 = bgt[(size_t)e * HDIM + col], bg1 = bgt[(size_t)e * HDIM + col + 1];
            int r0 = m0 + wm + mt * 16 + gq;
            if (r0 < cnt) {
                float h0 = cf[mt][nt][0] + bf0, h1 = cf[mt][nt][1] + bf1;
                float q0 = cg[mt][nt][0] + bg0, q1 = cg[mt][nt][1] + bg1;
                float2 u;
                u.x = to_tf32(h0 * (q0 / (1.f + expf(-q0))));
                u.y = to_tf32(h1 * (q1 / (1.f + expf(-q1))));
                *(float2*)(U + (size_t)r0 * HDIM + col) = u;
            }
            int r1 = r0 + 8;
            if (r1 < cnt) {
                float h0 = cf[mt][nt][2] + bf0, h1 = cf[mt][nt][3] + bf1;
                float q0 = cg[mt][nt][2] + bg0, q1 = cg[mt][nt][3] + bg1;
                float2 u;
                u.x = to_tf32(h0 * (q0 / (1.f + expf(-q0))));
                u.y = to_tf32(h1 * (q1 / (1.f + expf(-q1))));
                *(float2*)(U + (size_t)r1 * HDIM + col) = u;
            }
        }
    }
}

// ================= GEMM2: proj, block 128x128, warp 64x32, BK=32, cp.async 3-stage, split-K=2 =================
// per stage: A 128*36 | B 32*136 = 8960 floats = 35840 B; 3 stages = 107520 B
#define G2_AS  4608
#define G2_BS  4352
#define G2_STG (G2_AS + G2_BS)
#define G2_SMEM_BYTES (3 * G2_STG * 4)
#define SPLITK 1536

__global__ __launch_bounds__(256, 2) void gemm2_kernel(const float* __restrict__ wpr,
                                                       const float* __restrict__ bpr) {
    extern __shared__ float smem[];
    const int e     = blockIdx.z >> 1;
    const int split = blockIdx.z & 1;
    const int cnt   = g_cnt[e];
    const int m0    = blockIdx.y * 128;
    if (m0 >= cnt) return;
    const int n0    = blockIdx.x * 128;
    const int kbase = split * SPLITK;

    const float* Ag = g_u + (size_t)e * CAP * HDIM + kbase;
    const float* Bp = wpr + (size_t)e * HDIM * CDIM + (size_t)kbase * CDIM;

    const int tid = threadIdx.x, lane = tid & 31, wid = tid >> 5;
    const int wm = (wid & 1) * 64, wn = (wid >> 1) * 32;
    const int gq = lane >> 2, tg = lane & 3;

    const uint32_t sBase = smem_u32(smem);

    auto load_stage = [&](int buf, int k0) {
        const uint32_t sA = sBase + (uint32_t)(buf * G2_STG) * 4;
        const uint32_t sB = sA + G2_AS * 4;
#pragma unroll
        for (int i = 0; i < 4; i++) {
            int v = tid + 256 * i, row = v >> 3, c4 = v & 7;
            int sz = (m0 + row < cnt) ? 16 : 0;
            cpa16(sA + (uint32_t)(row * 36 + c4 * 4) * 4,
                  Ag + (size_t)(m0 + row) * HDIM + k0 + c4 * 4, sz);
        }
#pragma unroll
        for (int i = 0; i < 4; i++) {
            int v = tid + 256 * i, row = v >> 5, c4 = v & 31;
            cpa16u(sB + (uint32_t)(row * 136 + c4 * 4) * 4,
                   Bp + (size_t)(k0 + row) * CDIM + n0 + c4 * 4);
        }
        cpa_commit();
    };

    float acc[4][4][4] = {};

    const int NIT = SPLITK / 32;  // 48
    load_stage(0, 0);
    load_stage(1, 32);

#pragma unroll 1
    for (int it = 0; it < NIT; ++it) {
        if (it + 1 < NIT) cpa_wait1(); else cpa_wait0();
        __syncthreads();
        if (it + 2 < NIT) load_stage((it + 2) % 3, (it + 2) * 32);

        const int cur = it % 3;
        const float* As = smem + cur * G2_STG;
        const float* Bs = As + G2_AS;
#pragma unroll
        for (int ks = 0; ks < 4; ks++) {
            const int kb = ks * 8;
            unsigned af[4][4];
#pragma unroll
            for (int mt = 0; mt < 4; mt++) {
                int r = wm + mt * 16 + gq;
                af[mt][0] = __float_as_uint(As[r * 36 + kb + tg]);
                af[mt][1] = __float_as_uint(As[(r + 8) * 36 + kb + tg]);
                af[mt][2] = __float_as_uint(As[r * 36 + kb + tg + 4]);
                af[mt][3] = __float_as_uint(As[(r + 8) * 36 + kb + tg + 4]);
            }
            unsigned bF[4][2];
#pragma unroll
            for (int nt = 0; nt < 4; nt++) {
                int cc = wn + nt * 8 + gq;
                bF[nt][0] = lds_tf32(&Bs[(kb + tg) * 136 + cc]);
                bF[nt][1] = lds_tf32(&Bs[(kb + tg + 4) * 136 + cc]);
            }
#pragma unroll
            for (int mt = 0; mt < 4; mt++)
#pragma unroll
                for (int nt = 0; nt < 4; nt++)
                    mma_tf32(acc[mt][nt], af[mt], bF[nt]);
        }
    }

    float* O = (split == 0 ? g_o : g_o2) + (size_t)e * CAP * CDIM;
#pragma unroll
    for (int mt = 0; mt < 4; mt++) {
#pragma unroll
        for (int nt = 0; nt < 4; nt++) {
            int col = n0 + wn + nt * 8 + tg * 2;
            float b0 = 0.f, b1 = 0.f;
            if (split == 0) {
                b0 = bpr[(size_t)e * CDIM + col];
                b1 = bpr[(size_t)e * CDIM + col + 1];
            }
            int r0 = m0 + wm + mt * 16 + gq;
            if (r0 < cnt) {
                float2 o; o.x = acc[mt][nt][0] + b0; o.y = acc[mt][nt][1] + b1;
                *(float2*)(O + (size_t)r0 * CDIM + col) = o;
            }
            int r1 = r0 + 8;
            if (r1 < cnt) {
                float2 o; o.x = acc[mt][nt][2] + b0; o.y = acc[mt][nt][3] + b1;
                *(float2*)(O + (size_t)r1 * CDIM + col) = o;
            }
        }
    }
}

// ---------------- kernel 4: deterministic combine (sums split-K halves) ----------------
__global__ __launch_bounds__(192) void combine_kernel(float* __restrict__ out) {
    const int t = blockIdx.x;
    const int c4 = threadIdx.x;
    const int i0 = g_pidx[2 * t + 0];
    const int i1 = g_pidx[2 * t + 1];
    const float p0 = g_prob[i0];
    const float p1 = g_prob[i1];
    const float4 a0 = reinterpret_cast<const float4*>(g_o  + (size_t)i0 * CDIM)[c4];
    const float4 a1 = reinterpret_cast<const float4*>(g_o2 + (size_t)i0 * CDIM)[c4];
    const float4 b0 = reinterpret_cast<const float4*>(g_o  + (size_t)i1 * CDIM)[c4];
    const float4 b1 = reinterpret_cast<const float4*>(g_o2 + (size_t)i1 * CDIM)[c4];
    float4 y;
    y.x = p0 * (a0.x + a1.x) + p1 * (b0.x + b1.x);
    y.y = p0 * (a0.y + a1.y) + p1 * (b0.y + b1.y);
    y.z = p0 * (a0.z + a1.z) + p1 * (b0.z + b1.z);
    y.w = p0 * (a0.w + a1.w) + p1 * (b0.w + b1.w);
    reinterpret_cast<float4*>(out + (size_t)t * CDIM)[c4] = y;
}

// ---------------- launch ----------------
extern "C" void kernel_launch(void* const* d_in, const int* in_sizes, int n_in,
                              void* d_out, int out_size) {
    const float* x    = (const float*)d_in[0];
    const float* wr   = (const float*)d_in[1];
    const float* wfc  = (const float*)d_in[2];
    const float* bfc  = (const float*)d_in[3];
    const float* wgt  = (const float*)d_in[4];
    const float* bgt  = (const float*)d_in[5];
    const float* wpr  = (const float*)d_in[6];
    const float* bpr  = (const float*)d_in[7];
    float* out = (float*)d_out;

    cudaFuncSetAttribute(gemm1_kernel, cudaFuncAttributeMaxDynamicSharedMemorySize, G1_SMEM_BYTES);
    cudaFuncSetAttribute(gemm2_kernel, cudaFuncAttributeMaxDynamicSharedMemorySize, G2_SMEM_BYTES);

    init_kernel<<<1, 32>>>();
    router_kernel<<<NTOK / 8, 256>>>(x, wr);
    gemm1_kernel<<<dim3(HDIM / 64, CAP / 128, EDIM), 256, G1_SMEM_BYTES>>>(wfc, bfc, wgt, bgt);
    gemm2_kernel<<<dim3(CDIM / 128, CAP / 128, EDIM * 2), 256, G2_SMEM_BYTES>>>(wpr, bpr);
    combine_kernel<<<NTOK, 192>>>(out);
}

// round 6
// speedup vs baseline: 1.0561x; 1.0561x over previous
#include <cuda_runtime.h>
#include <cuda_bf16.h>
#include <math.h>
#include <stdint.h>

// Problem constants
#define NTOK 2048
#define CDIM 768
#define EDIM 8
#define HDIM 3072
#define CAP  2048

// ---------------- scratch (static device memory; no allocations) ----------------
__device__ float g_xbuf[(size_t)EDIM * CAP * CDIM];   // gathered activations (tf32 RNA-rounded)
__device__ float g_u   [(size_t)EDIM * CAP * HDIM];   // h*silu(g) (tf32 RNA-rounded)
__device__ float g_o   [(size_t)EDIM * CAP * CDIM];   // proj out split 0
__device__ float g_o2  [(size_t)EDIM * CAP * CDIM];   // proj out split 1
__device__ int   g_cnt [EDIM];
__device__ float g_prob[EDIM * CAP];
__device__ int   g_pidx[2 * NTOK];

// ---------------- helpers ----------------
__device__ __forceinline__ float to_tf32(float x) {
    unsigned u;
    asm("cvt.rna.tf32.f32 %0, %1;" : "=r"(u) : "f"(x));
    return __uint_as_float(u);
}

__device__ __forceinline__ unsigned lds_tf32(const float* p) {
    return __float_as_uint(to_tf32(*p));
}

__device__ __forceinline__ void mma_tf32(float c[4], const unsigned a[4], const unsigned b[2]) {
    asm volatile(
        "mma.sync.aligned.m16n8k8.row.col.f32.tf32.tf32.f32 "
        "{%0,%1,%2,%3},{%4,%5,%6,%7},{%8,%9},{%0,%1,%2,%3};\n"
        : "+f"(c[0]), "+f"(c[1]), "+f"(c[2]), "+f"(c[3])
        : "r"(a[0]), "r"(a[1]), "r"(a[2]), "r"(a[3]), "r"(b[0]), "r"(b[1]));
}

// ldmatrix x4 b16 — for tf32 each register is one 32-bit element (a b16 pair)
__device__ __forceinline__ void ldsm_x4(unsigned r[4], uint32_t addr) {
    asm volatile("ldmatrix.sync.aligned.m8n8.x4.shared.b16 {%0,%1,%2,%3}, [%4];"
                 : "=r"(r[0]), "=r"(r[1]), "=r"(r[2]), "=r"(r[3]) : "r"(addr));
}

__device__ __forceinline__ void cpa16(uint32_t dst, const void* src, int sz) {
    asm volatile("cp.async.cg.shared.global [%0], [%1], 16, %2;"
                 :: "r"(dst), "l"(src), "r"(sz));
}
__device__ __forceinline__ void cpa16u(uint32_t dst, const void* src) {
    asm volatile("cp.async.cg.shared.global [%0], [%1], 16;"
                 :: "r"(dst), "l"(src));
}
__device__ __forceinline__ void cpa_commit() { asm volatile("cp.async.commit_group;"); }
__device__ __forceinline__ void cpa_wait1()  { asm volatile("cp.async.wait_group 1;" ::: "memory"); }
__device__ __forceinline__ void cpa_wait0()  { asm volatile("cp.async.wait_group 0;" ::: "memory"); }

__device__ __forceinline__ uint32_t smem_u32(const void* p) {
    return (uint32_t)__cvta_generic_to_shared(p);
}

// ---------------- kernel 0: init counters ----------------
__global__ void init_kernel() {
    if (threadIdx.x < EDIM) g_cnt[threadIdx.x] = 0;
}

// ---------------- kernel 1: router + dispatch/gather (tf32 RNA-rounded gather) ----------------
__global__ __launch_bounds__(256) void router_kernel(const float* __restrict__ x,
                                                     const float* __restrict__ wr) {
    const int t = blockIdx.x * 8 + (threadIdx.x >> 5);
    if (t >= NTOK) return;
    const int lane = threadIdx.x & 31;
    const float* xr = x + (size_t)t * CDIM;

    float acc[EDIM];
#pragma unroll
    for (int e = 0; e < EDIM; e++) acc[e] = 0.f;
#pragma unroll
    for (int j = 0; j < CDIM / 32; j++) {
        int i = lane + 32 * j;
        float xv = xr[i];
        const float4* w4 = reinterpret_cast<const float4*>(wr + (size_t)i * EDIM);
        float4 w0 = w4[0], w1 = w4[1];
        acc[0] += xv * w0.x; acc[1] += xv * w0.y; acc[2] += xv * w0.z; acc[3] += xv * w0.w;
        acc[4] += xv * w1.x; acc[5] += xv * w1.y; acc[6] += xv * w1.z; acc[7] += xv * w1.w;
    }
#pragma unroll
    for (int off = 16; off > 0; off >>= 1) {
#pragma unroll
        for (int e = 0; e < EDIM; e++) acc[e] += __shfl_xor_sync(0xffffffffu, acc[e], off);
    }
    int e0 = 0; float l0 = acc[0];
#pragma unroll
    for (int e = 1; e < EDIM; e++) if (acc[e] > l0) { l0 = acc[e]; e0 = e; }
    int e1 = -1; float l1 = -INFINITY;
#pragma unroll
    for (int e = 0; e < EDIM; e++) if (e != e0 && acc[e] > l1) { l1 = acc[e]; e1 = e; }

    float ex = expf(l1 - l0);
    float p0 = 1.f / (1.f + ex);
    float p1 = ex * p0;

    int s0 = 0, s1 = 0;
    if (lane == 0) {
        s0 = atomicAdd(&g_cnt[e0], 1);
        s1 = atomicAdd(&g_cnt[e1], 1);
        g_prob[e0 * CAP + s0] = p0;
        g_prob[e1 * CAP + s1] = p1;
        g_pidx[2 * t + 0] = e0 * CAP + s0;
        g_pidx[2 * t + 1] = e1 * CAP + s1;
    }
    s0 = __shfl_sync(0xffffffffu, s0, 0);
    s1 = __shfl_sync(0xffffffffu, s1, 0);

    float* d0 = g_xbuf + ((size_t)e0 * CAP + s0) * CDIM;
    float* d1 = g_xbuf + ((size_t)e1 * CAP + s1) * CDIM;
#pragma unroll
    for (int j = 0; j < CDIM / 32; j++) {
        int i = lane + 32 * j;
        float v = to_tf32(xr[i]);
        d0[i] = v;
        d1[i] = v;
    }
}

// ================= GEMM1: fused fc+gate, block 128x64 (x2), BK=32, cp.async 2-stage =================
// smem (floats): As[2][128*36] | Bf[2][32*72] | Bg[2][32*72]  = 73728 bytes
#define G1_SMEM_BYTES 73728
#define G1_AS   4608
#define G1_BS   2304
#define G1_BF0  (2 * G1_AS)
#define G1_BG0  (G1_BF0 + 2 * G1_BS)

__global__ __launch_bounds__(256, 2) void gemm1_kernel(const float* __restrict__ wfc,
                                                       const float* __restrict__ bfc,
                                                       const float* __restrict__ wgt,
                                                       const float* __restrict__ bgt) {
    extern __shared__ float smem[];
    const int e   = blockIdx.z;
    const int cnt = g_cnt[e];
    const int m0  = blockIdx.y * 128;
    if (m0 >= cnt) return;
    const int n0  = blockIdx.x * 64;

    const float* Ag = g_xbuf + (size_t)e * CAP * CDIM;
    const float* B0 = wfc + (size_t)e * CDIM * HDIM;
    const float* B1 = wgt + (size_t)e * CDIM * HDIM;

    const int tid = threadIdx.x, lane = tid & 31, wid = tid >> 5;
    const int wm = (wid & 3) * 32, wn = (wid >> 2) * 32;
    const int gq = lane >> 2, tg = lane & 3;

    const uint32_t sA  = smem_u32(smem);
    const uint32_t sBf = sA + G1_BF0 * 4;
    const uint32_t sBg = sA + G1_BG0 * 4;

    // ldmatrix lane offset: rows lane&15, k-half (lane>>4)*4
    const uint32_t laneA = (uint32_t)(((lane & 15) * 36 + (lane >> 4) * 4) * 4);

    auto load_stage = [&](int buf, int k0) {
#pragma unroll
        for (int i = 0; i < 4; i++) {
            int v = tid + 256 * i, row = v >> 3, c4 = v & 7;
            int sz = (m0 + row < cnt) ? 16 : 0;
            cpa16(sA + (uint32_t)(buf * G1_AS + row * 36 + c4 * 4) * 4,
                  Ag + (size_t)(m0 + row) * CDIM + k0 + c4 * 4, sz);
        }
#pragma unroll
        for (int i = 0; i < 2; i++) {
            int v = tid + 256 * i, row = v >> 4, c4 = v & 15;
            size_t off = (size_t)(k0 + row) * HDIM + n0 + c4 * 4;
            uint32_t so = (uint32_t)(buf * G1_BS + row * 72 + c4 * 4) * 4;
            cpa16u(sBf + so, B0 + off);
            cpa16u(sBg + so, B1 + off);
        }
        cpa_commit();
    };

    float cf[2][4][4] = {};
    float cg[2][4][4] = {};

    const int NIT = CDIM / 32;  // 24
    load_stage(0, 0);
    load_stage(1, 32);

#pragma unroll 1
    for (int it = 0; it < NIT; ++it) {
        const int cur = it & 1;
        if (it + 1 < NIT) cpa_wait1(); else cpa_wait0();
        __syncthreads();

        const uint32_t aB = sA + (uint32_t)(cur * G1_AS) * 4;
        const float* Bf = smem + G1_BF0 + cur * G1_BS;
        const float* Bg = smem + G1_BG0 + cur * G1_BS;

        // register double-buffered fragments over ks
        unsigned uA[2][2][4], uBf[2][4][2], uBg[2][4][2];

        auto ldfrag = [&](int ks, int s) {
            const int kb = ks * 8;
#pragma unroll
            for (int mt = 0; mt < 2; mt++)
                ldsm_x4(uA[s][mt], aB + (uint32_t)(((wm + mt * 16) * 36 + kb) * 4) + laneA);
#pragma unroll
            for (int nt = 0; nt < 4; nt++) {
                int cc = wn + nt * 8 + gq;
                uBf[s][nt][0] = lds_tf32(&Bf[(kb + tg) * 72 + cc]);
                uBf[s][nt][1] = lds_tf32(&Bf[(kb + tg + 4) * 72 + cc]);
                uBg[s][nt][0] = lds_tf32(&Bg[(kb + tg) * 72 + cc]);
                uBg[s][nt][1] = lds_tf32(&Bg[(kb + tg + 4) * 72 + cc]);
            }
        };

        ldfrag(0, 0);
#pragma unroll
        for (int ks = 0; ks < 4; ks++) {
            const int s = ks & 1;
            if (ks < 3) ldfrag(ks + 1, s ^ 1);
#pragma unroll
            for (int mt = 0; mt < 2; mt++)
#pragma unroll
                for (int nt = 0; nt < 4; nt++) {
                    mma_tf32(cf[mt][nt], uA[s][mt], uBf[s][nt]);
                    mma_tf32(cg[mt][nt], uA[s][mt], uBg[s][nt]);
                }
        }
        __syncthreads();
        if (it + 2 < NIT) load_stage(cur, (it + 2) * 32);
    }

    // epilogue: u = (h+bfc) * silu(g+bg), RNA tf32-rounded
    float* U = g_u + (size_t)e * CAP * HDIM;
#pragma unroll
    for (int mt = 0; mt < 2; mt++) {
#pragma unroll
        for (int nt = 0; nt < 4; nt++) {
            int col = n0 + wn + nt * 8 + tg * 2;
            float bf0 = bfc[(size_t)e * HDIM + col], bf1 = bfc[(size_t)e * HDIM + col + 1];
            float bg0 = bgt[(size_t)e * HDIM + col], bg1 = bgt[(size_t)e * HDIM + col + 1];
            int r0 = m0 + wm + mt * 16 + gq;
            if (r0 < cnt) {
                float h0 = cf[mt][nt][0] + bf0, h1 = cf[mt][nt][1] + bf1;
                float q0 = cg[mt][nt][0] + bg0, q1 = cg[mt][nt][1] + bg1;
                float2 u;
                u.x = to_tf32(h0 * (q0 / (1.f + expf(-q0))));
                u.y = to_tf32(h1 * (q1 / (1.f + expf(-q1))));
                *(float2*)(U + (size_t)r0 * HDIM + col) = u;
            }
            int r1 = r0 + 8;
            if (r1 < cnt) {
                float h0 = cf[mt][nt][2] + bf0, h1 = cf[mt][nt][3] + bf1;
                float q0 = cg[mt][nt][2] + bg0, q1 = cg[mt][nt][3] + bg1;
                float2 u;
                u.x = to_tf32(h0 * (q0 / (1.f + expf(-q0))));
                u.y = to_tf32(h1 * (q1 / (1.f + expf(-q1))));
                *(float2*)(U + (size_t)r1 * HDIM + col) = u;
            }
        }
    }
}

// ================= GEMM2: proj, block 128x128, warp 64x32, BK=32, cp.async 2-stage, split-K=2 =================
#define G2_SMEM_BYTES 71680
#define G2_AS 4608
#define G2_BS 4352
#define G2_B0 (2 * G2_AS)
#define SPLITK 1536

__global__ __launch_bounds__(256, 2) void gemm2_kernel(const float* __restrict__ wpr,
                                                       const float* __restrict__ bpr) {
    extern __shared__ float smem[];
    const int e     = blockIdx.z >> 1;
    const int split = blockIdx.z & 1;
    const int cnt   = g_cnt[e];
    const int m0    = blockIdx.y * 128;
    if (m0 >= cnt) return;
    const int n0    = blockIdx.x * 128;
    const int kbase = split * SPLITK;

    const float* Ag = g_u + (size_t)e * CAP * HDIM + kbase;
    const float* Bp = wpr + (size_t)e * HDIM * CDIM + (size_t)kbase * CDIM;

    const int tid = threadIdx.x, lane = tid & 31, wid = tid >> 5;
    const int wm = (wid & 1) * 64, wn = (wid >> 1) * 32;
    const int gq = lane >> 2, tg = lane & 3;

    const uint32_t sA = smem_u32(smem);
    const uint32_t sB = sA + G2_B0 * 4;
    const uint32_t laneA = (uint32_t)(((lane & 15) * 36 + (lane >> 4) * 4) * 4);

    auto load_stage = [&](int buf, int k0) {
#pragma unroll
        for (int i = 0; i < 4; i++) {
            int v = tid + 256 * i, row = v >> 3, c4 = v & 7;
            int sz = (m0 + row < cnt) ? 16 : 0;
            cpa16(sA + (uint32_t)(buf * G2_AS + row * 36 + c4 * 4) * 4,
                  Ag + (size_t)(m0 + row) * HDIM + k0 + c4 * 4, sz);
        }
#pragma unroll
        for (int i = 0; i < 4; i++) {
            int v = tid + 256 * i, row = v >> 5, c4 = v & 31;
            cpa16u(sB + (uint32_t)(buf * G2_BS + row * 136 + c4 * 4) * 4,
                   Bp + (size_t)(k0 + row) * CDIM + n0 + c4 * 4);
        }
        cpa_commit();
    };

    float acc[4][4][4] = {};

    const int NIT = SPLITK / 32;  // 48
    load_stage(0, 0);
    load_stage(1, 32);

#pragma unroll 1
    for (int it = 0; it < NIT; ++it) {
        const int cur = it & 1;
        if (it + 1 < NIT) cpa_wait1(); else cpa_wait0();
        __syncthreads();

        const uint32_t aB = sA + (uint32_t)(cur * G2_AS) * 4;
        const float* Bs = smem + G2_B0 + cur * G2_BS;

        unsigned uA[2][4][4], uB[2][4][2];

        auto ldfrag = [&](int ks, int s) {
            const int kb = ks * 8;
#pragma unroll
            for (int mt = 0; mt < 4; mt++)
                ldsm_x4(uA[s][mt], aB + (uint32_t)(((wm + mt * 16) * 36 + kb) * 4) + laneA);
#pragma unroll
            for (int nt = 0; nt < 4; nt++) {
                int cc = wn + nt * 8 + gq;
                uB[s][nt][0] = lds_tf32(&Bs[(kb + tg) * 136 + cc]);
                uB[s][nt][1] = lds_tf32(&Bs[(kb + tg + 4) * 136 + cc]);
            }
        };

        ldfrag(0, 0);
#pragma unroll
        for (int ks = 0; ks < 4; ks++) {
            const int s = ks & 1;
            if (ks < 3) ldfrag(ks + 1, s ^ 1);
#pragma unroll
            for (int mt = 0; mt < 4; mt++)
#pragma unroll
                for (int nt = 0; nt < 4; nt++)
                    mma_tf32(acc[mt][nt], uA[s][mt], uB[s][nt]);
        }
        __syncthreads();
        if (it + 2 < NIT) load_stage(cur, (it + 2) * 32);
    }

    float* O = (split == 0 ? g_o : g_o2) + (size_t)e * CAP * CDIM;
#pragma unroll
    for (int mt = 0; mt < 4; mt++) {
#pragma unroll
        for (int nt = 0; nt < 4; nt++) {
            int col = n0 + wn + nt * 8 + tg * 2;
            float b0 = 0.f, b1 = 0.f;
            if (split == 0) {
                b0 = bpr[(size_t)e * CDIM + col];
                b1 = bpr[(size_t)e * CDIM + col + 1];
            }
            int r0 = m0 + wm + mt * 16 + gq;
            if (r0 < cnt) {
                float2 o; o.x = acc[mt][nt][0] + b0; o.y = acc[mt][nt][1] + b1;
                *(float2*)(O + (size_t)r0 * CDIM + col) = o;
            }
            int r1 = r0 + 8;
            if (r1 < cnt) {
                float2 o; o.x = acc[mt][nt][2] + b0; o.y = acc[mt][nt][3] + b1;
                *(float2*)(O + (size_t)r1 * CDIM + col) = o;
            }
        }
    }
}

// ---------------- kernel 4: deterministic combine (sums split-K halves) ----------------
__global__ __launch_bounds__(192) void combine_kernel(float* __restrict__ out) {
    const int t = blockIdx.x;
    const int c4 = threadIdx.x;
    const int i0 = g_pidx[2 * t + 0];
    const int i1 = g_pidx[2 * t + 1];
    const float p0 = g_prob[i0];
    const float p1 = g_prob[i1];
    const float4 a0 = reinterpret_cast<const float4*>(g_o  + (size_t)i0 * CDIM)[c4];
    const float4 a1 = reinterpret_cast<const float4*>(g_o2 + (size_t)i0 * CDIM)[c4];
    const float4 b0 = reinterpret_cast<const float4*>(g_o  + (size_t)i1 * CDIM)[c4];
    const float4 b1 = reinterpret_cast<const float4*>(g_o2 + (size_t)i1 * CDIM)[c4];
    float4 y;
    y.x = p0 * (a0.x + a1.x) + p1 * (b0.x + b1.x);
    y.y = p0 * (a0.y + a1.y) + p1 * (b0.y + b1.y);
    y.z = p0 * (a0.z + a1.z) + p1 * (b0.z + b1.z);
    y.w = p0 * (a0.w + a1.w) + p1 * (b0.w + b1.w);
    reinterpret_cast<float4*>(out + (size_t)t * CDIM)[c4] = y;
}

// ---------------- launch ----------------
extern "C" void kernel_launch(void* const* d_in, const int* in_sizes, int n_in,
                              void* d_out, int out_size) {
    const float* x    = (const float*)d_in[0];
    const float* wr   = (const float*)d_in[1];
    const float* wfc  = (const float*)d_in[2];
    const float* bfc  = (const float*)d_in[3];
    const float* wgt  = (const float*)d_in[4];
    const float* bgt  = (const float*)d_in[5];
    const float* wpr  = (const float*)d_in[6];
    const float* bpr  = (const float*)d_in[7];
    float* out = (float*)d_out;

    cudaFuncSetAttribute(gemm1_kernel, cudaFuncAttributeMaxDynamicSharedMemorySize, G1_SMEM_BYTES);
    cudaFuncSetAttribute(gemm2_kernel, cudaFuncAttributeMaxDynamicSharedMemorySize, G2_SMEM_BYTES);

    init_kernel<<<1, 32>>>();
    router_kernel<<<NTOK / 8, 256>>>(x, wr);
    gemm1_kernel<<<dim3(HDIM / 64, CAP / 128, EDIM), 256, G1_SMEM_BYTES>>>(wfc, bfc, wgt, bgt);
    gemm2_kernel<<<dim3(CDIM / 128, CAP / 128, EDIM * 2), 256, G2_SMEM_BYTES>>>(wpr, bpr);
    combine_kernel<<<NTOK, 192>>>(out);
}

// round 7
// speedup vs baseline: 1.3817x; 1.3082x over previous
#include <cuda_runtime.h>
#include <cuda_fp16.h>
#include <math.h>
#include <stdint.h>

// Problem constants
#define NTOK 2048
#define CDIM 768
#define EDIM 8
#define HDIM 3072
#define CAP  2048

// ---------------- scratch (static device memory; no allocations) ----------------
__device__ __half g_xbuf[(size_t)EDIM * CAP * CDIM];   // gathered activations (fp16)
__device__ __half g_u   [(size_t)EDIM * CAP * HDIM];   // h*silu(g) (fp16)
__device__ float  g_o   [(size_t)EDIM * CAP * CDIM];   // proj out split 0
__device__ float  g_o2  [(size_t)EDIM * CAP * CDIM];   // proj out split 1
__device__ __half g_wfcH[(size_t)EDIM * CDIM * HDIM];  // fp16 weights
__device__ __half g_wgtH[(size_t)EDIM * CDIM * HDIM];
__device__ __half g_wprH[(size_t)EDIM * HDIM * CDIM];
__device__ int    g_cnt [EDIM];
__device__ float  g_prob[EDIM * CAP];
__device__ int    g_pidx[2 * NTOK];

// ---------------- helpers ----------------
__device__ __forceinline__ void mma_f16(float c[4], const unsigned a[4], const unsigned b[2]) {
    asm volatile(
        "mma.sync.aligned.m16n8k16.row.col.f32.f16.f16.f32 "
        "{%0,%1,%2,%3},{%4,%5,%6,%7},{%8,%9},{%0,%1,%2,%3};\n"
        : "+f"(c[0]), "+f"(c[1]), "+f"(c[2]), "+f"(c[3])
        : "r"(a[0]), "r"(a[1]), "r"(a[2]), "r"(a[3]), "r"(b[0]), "r"(b[1]));
}

__device__ __forceinline__ void ldsm_x4(unsigned r[4], uint32_t addr) {
    asm volatile("ldmatrix.sync.aligned.m8n8.x4.shared.b16 {%0,%1,%2,%3}, [%4];"
                 : "=r"(r[0]), "=r"(r[1]), "=r"(r[2]), "=r"(r[3]) : "r"(addr));
}
__device__ __forceinline__ void ldsm_x4t(unsigned r[4], uint32_t addr) {
    asm volatile("ldmatrix.sync.aligned.m8n8.x4.trans.shared.b16 {%0,%1,%2,%3}, [%4];"
                 : "=r"(r[0]), "=r"(r[1]), "=r"(r[2]), "=r"(r[3]) : "r"(addr));
}

__device__ __forceinline__ void cpa16(uint32_t dst, const void* src, int sz) {
    asm volatile("cp.async.cg.shared.global [%0], [%1], 16, %2;"
                 :: "r"(dst), "l"(src), "r"(sz));
}
__device__ __forceinline__ void cpa16u(uint32_t dst, const void* src) {
    asm volatile("cp.async.cg.shared.global [%0], [%1], 16;"
                 :: "r"(dst), "l"(src));
}
__device__ __forceinline__ void cpa_commit() { asm volatile("cp.async.commit_group;"); }
__device__ __forceinline__ void cpa_wait1()  { asm volatile("cp.async.wait_group 1;" ::: "memory"); }
__device__ __forceinline__ void cpa_wait0()  { asm volatile("cp.async.wait_group 0;" ::: "memory"); }

__device__ __forceinline__ uint32_t smem_u32(const void* p) {
    return (uint32_t)__cvta_generic_to_shared(p);
}

// ---------------- kernel 0: init counters ----------------
__global__ void init_kernel() {
    if (threadIdx.x < EDIM) g_cnt[threadIdx.x] = 0;
}

// ---------------- weight convert: f32 -> f16 (grid covers n/4 float4s) ----------------
__global__ __launch_bounds__(256) void convert_kernel(const float4* __restrict__ src,
                                                      __half2* __restrict__ dst) {
    size_t i = (size_t)blockIdx.x * 256 + threadIdx.x;
    float4 v = src[i];
    dst[2 * i + 0] = __floats2half2_rn(v.x, v.y);
    dst[2 * i + 1] = __floats2half2_rn(v.z, v.w);
}

// ---------------- kernel 1: router + dispatch/gather (fp16 gather) ----------------
__global__ __launch_bounds__(256) void router_kernel(const float* __restrict__ x,
                                                     const float* __restrict__ wr) {
    const int t = blockIdx.x * 8 + (threadIdx.x >> 5);
    if (t >= NTOK) return;
    const int lane = threadIdx.x & 31;
    const float* xr = x + (size_t)t * CDIM;

    float acc[EDIM];
#pragma unroll
    for (int e = 0; e < EDIM; e++) acc[e] = 0.f;
#pragma unroll
    for (int j = 0; j < CDIM / 32; j++) {
        int i = lane + 32 * j;
        float xv = xr[i];
        const float4* w4 = reinterpret_cast<const float4*>(wr + (size_t)i * EDIM);
        float4 w0 = w4[0], w1 = w4[1];
        acc[0] += xv * w0.x; acc[1] += xv * w0.y; acc[2] += xv * w0.z; acc[3] += xv * w0.w;
        acc[4] += xv * w1.x; acc[5] += xv * w1.y; acc[6] += xv * w1.z; acc[7] += xv * w1.w;
    }
#pragma unroll
    for (int off = 16; off > 0; off >>= 1) {
#pragma unroll
        for (int e = 0; e < EDIM; e++) acc[e] += __shfl_xor_sync(0xffffffffu, acc[e], off);
    }
    int e0 = 0; float l0 = acc[0];
#pragma unroll
    for (int e = 1; e < EDIM; e++) if (acc[e] > l0) { l0 = acc[e]; e0 = e; }
    int e1 = -1; float l1 = -INFINITY;
#pragma unroll
    for (int e = 0; e < EDIM; e++) if (e != e0 && acc[e] > l1) { l1 = acc[e]; e1 = e; }

    float ex = expf(l1 - l0);
    float p0 = 1.f / (1.f + ex);
    float p1 = ex * p0;

    int s0 = 0, s1 = 0;
    if (lane == 0) {
        s0 = atomicAdd(&g_cnt[e0], 1);
        s1 = atomicAdd(&g_cnt[e1], 1);
        g_prob[e0 * CAP + s0] = p0;
        g_prob[e1 * CAP + s1] = p1;
        g_pidx[2 * t + 0] = e0 * CAP + s0;
        g_pidx[2 * t + 1] = e1 * CAP + s1;
    }
    s0 = __shfl_sync(0xffffffffu, s0, 0);
    s1 = __shfl_sync(0xffffffffu, s1, 0);

    __half2* d0 = reinterpret_cast<__half2*>(g_xbuf + ((size_t)e0 * CAP + s0) * CDIM);
    __half2* d1 = reinterpret_cast<__half2*>(g_xbuf + ((size_t)e1 * CAP + s1) * CDIM);
    const float2* x2 = reinterpret_cast<const float2*>(xr);
#pragma unroll
    for (int j = 0; j < CDIM / 64; j++) {
        int i = lane + 32 * j;
        float2 v = x2[i];
        __half2 h = __floats2half2_rn(v.x, v.y);
        d0[i] = h;
        d1[i] = h;
    }
}

// ======== GEMM1: fused fc+gate, block 128x64(x2), BK=32, fp16 mma, cp.async 2-stage ========
// smem halves: A[2][128*40] | Bf[2][32*72] | Bg[2][32*72]  -> 19456 halves = 38912 B
#define G1_AH    5120            // halves per A stage
#define G1_BH    2304            // halves per B stage (each matrix)
#define G1_BF0H  (2 * G1_AH)
#define G1_BG0H  (G1_BF0H + 2 * G1_BH)
#define G1_SMEM_BYTES ((G1_BG0H + 2 * G1_BH) * 2)

__global__ __launch_bounds__(256, 2) void gemm1_kernel(const float* __restrict__ bfc,
                                                       const float* __restrict__ bgt) {
    extern __shared__ __half smh[];
    const int e   = blockIdx.z;
    const int cnt = g_cnt[e];
    const int m0  = blockIdx.y * 128;
    if (m0 >= cnt) return;
    const int n0  = blockIdx.x * 64;

    const __half* Ag = g_xbuf + (size_t)e * CAP * CDIM;
    const __half* B0 = g_wfcH + (size_t)e * CDIM * HDIM;
    const __half* B1 = g_wgtH + (size_t)e * CDIM * HDIM;

    const int tid = threadIdx.x, lane = tid & 31, wid = tid >> 5;
    const int wm = (wid & 3) * 32, wn = (wid >> 2) * 32;
    const int gq = lane >> 2, tg = lane & 3;
    const int grp = lane >> 3, rin = lane & 7;

    const uint32_t sBase = smem_u32(smh);

    auto load_stage = [&](int buf, int k0) {
        // A: 128 rows x 64B = 512 chunks, 2/thread
#pragma unroll
        for (int i = 0; i < 2; i++) {
            int v = tid + 256 * i, row = v >> 2, c16 = v & 3;
            int sz = (m0 + row < cnt) ? 16 : 0;
            cpa16(sBase + (uint32_t)(buf * G1_AH + row * 40 + c16 * 8) * 2,
                  Ag + (size_t)(m0 + row) * CDIM + k0 + c16 * 8, sz);
        }
        // B each: 32 rows x 128B = 256 chunks, 1/thread per matrix
        {
            int row = tid >> 3, c16 = tid & 7;
            size_t off = (size_t)(k0 + row) * HDIM + n0 + c16 * 8;
            cpa16u(sBase + (uint32_t)(G1_BF0H + buf * G1_BH + row * 72 + c16 * 8) * 2, B0 + off);
            cpa16u(sBase + (uint32_t)(G1_BG0H + buf * G1_BH + row * 72 + c16 * 8) * 2, B1 + off);
        }
        cpa_commit();
    };

    float cf[2][4][4] = {};
    float cg[2][4][4] = {};

    const int NIT = CDIM / 32;  // 24
    load_stage(0, 0);
    load_stage(1, 32);

#pragma unroll 1
    for (int it = 0; it < NIT; ++it) {
        const int cur = it & 1;
        if (it + 1 < NIT) cpa_wait1(); else cpa_wait0();
        __syncthreads();

        const uint32_t aB  = sBase + (uint32_t)(cur * G1_AH) * 2;
        const uint32_t bfB = sBase + (uint32_t)(G1_BF0H + cur * G1_BH) * 2;
        const uint32_t bgB = sBase + (uint32_t)(G1_BG0H + cur * G1_BH) * 2;

        unsigned uA[2][2][4], uBf[2][4][2], uBg[2][4][2];

        auto ldfrag = [&](int ks, int s) {
            const int kb = ks * 16;
#pragma unroll
            for (int mt = 0; mt < 2; mt++) {
                int r = wm + mt * 16 + (grp & 1) * 8 + rin;
                ldsm_x4(uA[s][mt], aB + (uint32_t)((r * 40 + kb + (grp >> 1) * 8) * 2));
            }
#pragma unroll
            for (int p = 0; p < 2; p++) {
                int kr = kb + (grp & 1) * 8 + rin;
                int cc = wn + p * 16 + (grp >> 1) * 8;
                unsigned r4[4];
                ldsm_x4t(r4, bfB + (uint32_t)((kr * 72 + cc) * 2));
                uBf[s][2 * p + 0][0] = r4[0]; uBf[s][2 * p + 0][1] = r4[1];
                uBf[s][2 * p + 1][0] = r4[2]; uBf[s][2 * p + 1][1] = r4[3];
                ldsm_x4t(r4, bgB + (uint32_t)((kr * 72 + cc) * 2));
                uBg[s][2 * p + 0][0] = r4[0]; uBg[s][2 * p + 0][1] = r4[1];
                uBg[s][2 * p + 1][0] = r4[2]; uBg[s][2 * p + 1][1] = r4[3];
            }
        };

        ldfrag(0, 0);
#pragma unroll
        for (int ks = 0; ks < 2; ks++) {
            const int s = ks & 1;
            if (ks < 1) ldfrag(ks + 1, s ^ 1);
#pragma unroll
            for (int mt = 0; mt < 2; mt++)
#pragma unroll
                for (int nt = 0; nt < 4; nt++) {
                    mma_f16(cf[mt][nt], uA[s][mt], uBf[s][nt]);
                    mma_f16(cg[mt][nt], uA[s][mt], uBg[s][nt]);
                }
        }
        __syncthreads();
        if (it + 2 < NIT) load_stage(cur, (it + 2) * 32);
    }

    // epilogue: u = (h+bfc) * silu(g+bg) -> fp16
    __half* U = g_u + (size_t)e * CAP * HDIM;
#pragma unroll
    for (int mt = 0; mt < 2; mt++) {
#pragma unroll
        for (int nt = 0; nt < 4; nt++) {
            int col = n0 + wn + nt * 8 + tg * 2;
            float bf0 = bfc[(size_t)e * HDIM + col], bf1 = bfc[(size_t)e * HDIM + col + 1];
            float bg0 = bgt[(size_t)e * HDIM + col], bg1 = bgt[(size_t)e * HDIM + col + 1];
            int r0 = m0 + wm + mt * 16 + gq;
            if (r0 < cnt) {
                float h0 = cf[mt][nt][0] + bf0, h1 = cf[mt][nt][1] + bf1;
                float q0 = cg[mt][nt][0] + bg0, q1 = cg[mt][nt][1] + bg1;
                float u0 = h0 * (q0 / (1.f + expf(-q0)));
                float u1 = h1 * (q1 / (1.f + expf(-q1)));
                *reinterpret_cast<__half2*>(U + (size_t)r0 * HDIM + col) = __floats2half2_rn(u0, u1);
            }
            int r1 = r0 + 8;
            if (r1 < cnt) {
                float h0 = cf[mt][nt][2] + bf0, h1 = cf[mt][nt][3] + bf1;
                float q0 = cg[mt][nt][2] + bg0, q1 = cg[mt][nt][3] + bg1;
                float u0 = h0 * (q0 / (1.f + expf(-q0)));
                float u1 = h1 * (q1 / (1.f + expf(-q1)));
                *reinterpret_cast<__half2*>(U + (size_t)r1 * HDIM + col) = __floats2half2_rn(u0, u1);
            }
        }
    }
}

// ======== GEMM2: proj, block 128x128, warp 64x32, BK=32, fp16 mma, cp.async 2-stage, split-K=2 ========
// smem halves: A[2][128*40] | B[2][32*136] -> 18944 halves = 37888 B
#define G2_AH   5120
#define G2_BH   4352
#define G2_B0H  (2 * G2_AH)
#define G2_SMEM_BYTES ((G2_B0H + 2 * G2_BH) * 2)
#define SPLITK 1536

__global__ __launch_bounds__(256, 2) void gemm2_kernel(const float* __restrict__ bpr) {
    extern __shared__ __half smh[];
    const int e     = blockIdx.z >> 1;
    const int split = blockIdx.z & 1;
    const int cnt   = g_cnt[e];
    const int m0    = blockIdx.y * 128;
    if (m0 >= cnt) return;
    const int n0    = blockIdx.x * 128;
    const int kbase = split * SPLITK;

    const __half* Ag = g_u + (size_t)e * CAP * HDIM + kbase;
    const __half* Bp = g_wprH + (size_t)e * HDIM * CDIM + (size_t)kbase * CDIM;

    const int tid = threadIdx.x, lane = tid & 31, wid = tid >> 5;
    const int wm = (wid & 1) * 64, wn = (wid >> 1) * 32;
    const int gq = lane >> 2, tg = lane & 3;
    const int grp = lane >> 3, rin = lane & 7;

    const uint32_t sBase = smem_u32(smh);

    auto load_stage = [&](int buf, int k0) {
#pragma unroll
        for (int i = 0; i < 2; i++) {
            int v = tid + 256 * i, row = v >> 2, c16 = v & 3;
            int sz = (m0 + row < cnt) ? 16 : 0;
            cpa16(sBase + (uint32_t)(buf * G2_AH + row * 40 + c16 * 8) * 2,
                  Ag + (size_t)(m0 + row) * HDIM + k0 + c16 * 8, sz);
        }
#pragma unroll
        for (int i = 0; i < 2; i++) {
            int v = tid + 256 * i, row = v >> 4, c16 = v & 15;
            cpa16u(sBase + (uint32_t)(G2_B0H + buf * G2_BH + row * 136 + c16 * 8) * 2,
                   Bp + (size_t)(k0 + row) * CDIM + n0 + c16 * 8);
        }
        cpa_commit();
    };

    float acc[4][4][4] = {};

    const int NIT = SPLITK / 32;  // 48
    load_stage(0, 0);
    load_stage(1, 32);

#pragma unroll 1
    for (int it = 0; it < NIT; ++it) {
        const int cur = it & 1;
        if (it + 1 < NIT) cpa_wait1(); else cpa_wait0();
        __syncthreads();

        const uint32_t aB = sBase + (uint32_t)(cur * G2_AH) * 2;
        const uint32_t bB = sBase + (uint32_t)(G2_B0H + cur * G2_BH) * 2;

        unsigned uA[2][4][4], uB[2][4][2];

        auto ldfrag = [&](int ks, int s) {
            const int kb = ks * 16;
#pragma unroll
            for (int mt = 0; mt < 4; mt++) {
                int r = wm + mt * 16 + (grp & 1) * 8 + rin;
                ldsm_x4(uA[s][mt], aB + (uint32_t)((r * 40 + kb + (grp >> 1) * 8) * 2));
            }
#pragma unroll
            for (int p = 0; p < 2; p++) {
                int kr = kb + (grp & 1) * 8 + rin;
                int cc = wn + p * 16 + (grp >> 1) * 8;
                unsigned r4[4];
                ldsm_x4t(r4, bB + (uint32_t)((kr * 136 + cc) * 2));
                uB[s][2 * p + 0][0] = r4[0]; uB[s][2 * p + 0][1] = r4[1];
                uB[s][2 * p + 1][0] = r4[2]; uB[s][2 * p + 1][1] = r4[3];
            }
        };

        ldfrag(0, 0);
#pragma unroll
        for (int ks = 0; ks < 2; ks++) {
            const int s = ks & 1;
            if (ks < 1) ldfrag(ks + 1, s ^ 1);
#pragma unroll
            for (int mt = 0; mt < 4; mt++)
#pragma unroll
                for (int nt = 0; nt < 4; nt++)
                    mma_f16(acc[mt][nt], uA[s][mt], uB[s][nt]);
        }
        __syncthreads();
        if (it + 2 < NIT) load_stage(cur, (it + 2) * 32);
    }

    float* O = (split == 0 ? g_o : g_o2) + (size_t)e * CAP * CDIM;
#pragma unroll
    for (int mt = 0; mt < 4; mt++) {
#pragma unroll
        for (int nt = 0; nt < 4; nt++) {
            int col = n0 + wn + nt * 8 + tg * 2;
            float b0 = 0.f, b1 = 0.f;
            if (split == 0) {
                b0 = bpr[(size_t)e * CDIM + col];
                b1 = bpr[(size_t)e * CDIM + col + 1];
            }
            int r0 = m0 + wm + mt * 16 + gq;
            if (r0 < cnt) {
                float2 o; o.x = acc[mt][nt][0] + b0; o.y = acc[mt][nt][1] + b1;
                *(float2*)(O + (size_t)r0 * CDIM + col) = o;
            }
            int r1 = r0 + 8;
            if (r1 < cnt) {
                float2 o; o.x = acc[mt][nt][2] + b0; o.y = acc[mt][nt][3] + b1;
                *(float2*)(O + (size_t)r1 * CDIM + col) = o;
            }
        }
    }
}

// ---------------- kernel 4: deterministic combine (sums split-K halves) ----------------
__global__ __launch_bounds__(192) void combine_kernel(float* __restrict__ out) {
    const int t = blockIdx.x;
    const int c4 = threadIdx.x;
    const int i0 = g_pidx[2 * t + 0];
    const int i1 = g_pidx[2 * t + 1];
    const float p0 = g_prob[i0];
    const float p1 = g_prob[i1];
    const float4 a0 = reinterpret_cast<const float4*>(g_o  + (size_t)i0 * CDIM)[c4];
    const float4 a1 = reinterpret_cast<const float4*>(g_o2 + (size_t)i0 * CDIM)[c4];
    const float4 b0 = reinterpret_cast<const float4*>(g_o  + (size_t)i1 * CDIM)[c4];
    const float4 b1 = reinterpret_cast<const float4*>(g_o2 + (size_t)i1 * CDIM)[c4];
    float4 y;
    y.x = p0 * (a0.x + a1.x) + p1 * (b0.x + b1.x);
    y.y = p0 * (a0.y + a1.y) + p1 * (b0.y + b1.y);
    y.z = p0 * (a0.z + a1.z) + p1 * (b0.z + b1.z);
    y.w = p0 * (a0.w + a1.w) + p1 * (b0.w + b1.w);
    reinterpret_cast<float4*>(out + (size_t)t * CDIM)[c4] = y;
}

// ---------------- launch ----------------
extern "C" void kernel_launch(void* const* d_in, const int* in_sizes, int n_in,
                              void* d_out, int out_size) {
    const float* x    = (const float*)d_in[0];
    const float* wr   = (const float*)d_in[1];
    const float* wfc  = (const float*)d_in[2];
    const float* bfc  = (const float*)d_in[3];
    const float* wgt  = (const float*)d_in[4];
    const float* bgt  = (const float*)d_in[5];
    const float* wpr  = (const float*)d_in[6];
    const float* bpr  = (const float*)d_in[7];
    float* out = (float*)d_out;

    __half* wfcH; cudaGetSymbolAddress((void**)&wfcH, g_wfcH);
    __half* wgtH; cudaGetSymbolAddress((void**)&wgtH, g_wgtH);
    __half* wprH; cudaGetSymbolAddress((void**)&wprH, g_wprH);

    const int WELEMS = EDIM * CDIM * HDIM;      // 18,874,368
    const int CBLKS  = WELEMS / 4 / 256;        // 18432

    init_kernel<<<1, 32>>>();
    convert_kernel<<<CBLKS, 256>>>((const float4*)wfc, (__half2*)wfcH);
    convert_kernel<<<CBLKS, 256>>>((const float4*)wgt, (__half2*)wgtH);
    convert_kernel<<<CBLKS, 256>>>((const float4*)wpr, (__half2*)wprH);
    router_kernel<<<NTOK / 8, 256>>>(x, wr);
    gemm1_kernel<<<dim3(HDIM / 64, CAP / 128, EDIM), 256, G1_SMEM_BYTES>>>(bfc, bgt);
    gemm2_kernel<<<dim3(CDIM / 128, CAP / 128, EDIM * 2), 256, G2_SMEM_BYTES>>>(bpr);
    combine_kernel<<<NTOK, 192>>>(out);
}

// round 9
// speedup vs baseline: 1.4965x; 1.0831x over previous
#include <cuda_runtime.h>
#include <cuda_fp16.h>
#include <math.h>
#include <stdint.h>

// Problem constants
#define NTOK 2048
#define CDIM 768
#define EDIM 8
#define HDIM 3072
#define CAP  2048

// ---------------- scratch (static device memory; no allocations) ----------------
__device__ __half g_xbuf[(size_t)EDIM * CAP * CDIM];   // gathered activations (fp16)
__device__ __half g_u   [(size_t)EDIM * CAP * HDIM];   // h*silu(g) (fp16)
__device__ float  g_o   [(size_t)EDIM * CAP * CDIM];   // proj out split 0
__device__ float  g_o2  [(size_t)EDIM * CAP * CDIM];   // proj out split 1
__device__ float  g_o3  [(size_t)EDIM * CAP * CDIM];   // proj out split 2
__device__ __half g_wfcH[(size_t)EDIM * CDIM * HDIM];  // fp16 weights
__device__ __half g_wgtH[(size_t)EDIM * CDIM * HDIM];
__device__ __half g_wprH[(size_t)EDIM * HDIM * CDIM];
__device__ int    g_cnt [EDIM];
__device__ float  g_prob[EDIM * CAP];
__device__ int    g_pidx[2 * NTOK];

// ---------------- helpers ----------------
__device__ __forceinline__ void mma_f16(float c[4], const unsigned a[4], const unsigned b[2]) {
    asm volatile(
        "mma.sync.aligned.m16n8k16.row.col.f32.f16.f16.f32 "
        "{%0,%1,%2,%3},{%4,%5,%6,%7},{%8,%9},{%0,%1,%2,%3};\n"
        : "+f"(c[0]), "+f"(c[1]), "+f"(c[2]), "+f"(c[3])
        : "r"(a[0]), "r"(a[1]), "r"(a[2]), "r"(a[3]), "r"(b[0]), "r"(b[1]));
}

__device__ __forceinline__ void ldsm_x4(unsigned r[4], uint32_t addr) {
    asm volatile("ldmatrix.sync.aligned.m8n8.x4.shared.b16 {%0,%1,%2,%3}, [%4];"
                 : "=r"(r[0]), "=r"(r[1]), "=r"(r[2]), "=r"(r[3]) : "r"(addr));
}
__device__ __forceinline__ void ldsm_x4t(unsigned r[4], uint32_t addr) {
    asm volatile("ldmatrix.sync.aligned.m8n8.x4.trans.shared.b16 {%0,%1,%2,%3}, [%4];"
                 : "=r"(r[0]), "=r"(r[1]), "=r"(r[2]), "=r"(r[3]) : "r"(addr));
}

__device__ __forceinline__ void cpa16(uint32_t dst, const void* src, int sz) {
    asm volatile("cp.async.cg.shared.global [%0], [%1], 16, %2;"
                 :: "r"(dst), "l"(src), "r"(sz));
}
__device__ __forceinline__ void cpa16u(uint32_t dst, const void* src) {
    asm volatile("cp.async.cg.shared.global [%0], [%1], 16;"
                 :: "r"(dst), "l"(src));
}
__device__ __forceinline__ void cpa_commit() { asm volatile("cp.async.commit_group;"); }
__device__ __forceinline__ void cpa_wait1()  { asm volatile("cp.async.wait_group 1;" ::: "memory"); }
__device__ __forceinline__ void cpa_wait0()  { asm volatile("cp.async.wait_group 0;" ::: "memory"); }

__device__ __forceinline__ uint32_t smem_u32(const void* p) {
    return (uint32_t)__cvta_generic_to_shared(p);
}

// ---------------- kernel 0: init counters ----------------
__global__ void init_kernel() {
    if (threadIdx.x < EDIM) g_cnt[threadIdx.x] = 0;
}

// ---------------- weight convert: all three tensors in one launch ----------------
#define WQUARTS (EDIM * CDIM * HDIM / 4)       // float4 count per tensor: 4,718,592
#define CBLKS_PER (WQUARTS / 256)              // 18432 blocks per tensor

__global__ __launch_bounds__(256) void convert_all_kernel(const float4* __restrict__ wfc,
                                                          const float4* __restrict__ wgt,
                                                          const float4* __restrict__ wpr,
                                                          __half2* __restrict__ ofc,
                                                          __half2* __restrict__ ogt,
                                                          __half2* __restrict__ opr) {
    const int which = blockIdx.x / CBLKS_PER;
    const size_t i = (size_t)(blockIdx.x % CBLKS_PER) * 256 + threadIdx.x;
    const float4* src = (which == 0) ? wfc : (which == 1) ? wgt : wpr;
    __half2* dst = (which == 0) ? ofc : (which == 1) ? ogt : opr;
    float4 v = src[i];
    dst[2 * i + 0] = __floats2half2_rn(v.x, v.y);
    dst[2 * i + 1] = __floats2half2_rn(v.z, v.w);
}

// ---------------- kernel 1: router + dispatch/gather (fp16 gather) ----------------
__global__ __launch_bounds__(256) void router_kernel(const float* __restrict__ x,
                                                     const float* __restrict__ wr) {
    const int t = blockIdx.x * 8 + (threadIdx.x >> 5);
    if (t >= NTOK) return;
    const int lane = threadIdx.x & 31;
    const float* xr = x + (size_t)t * CDIM;

    float acc[EDIM];
#pragma unroll
    for (int e = 0; e < EDIM; e++) acc[e] = 0.f;
#pragma unroll
    for (int j = 0; j < CDIM / 32; j++) {
        int i = lane + 32 * j;
        float xv = xr[i];
        const float4* w4 = reinterpret_cast<const float4*>(wr + (size_t)i * EDIM);
        float4 w0 = w4[0], w1 = w4[1];
        acc[0] += xv * w0.x; acc[1] += xv * w0.y; acc[2] += xv * w0.z; acc[3] += xv * w0.w;
        acc[4] += xv * w1.x; acc[5] += xv * w1.y; acc[6] += xv * w1.z; acc[7] += xv * w1.w;
    }
#pragma unroll
    for (int off = 16; off > 0; off >>= 1) {
#pragma unroll
        for (int e = 0; e < EDIM; e++) acc[e] += __shfl_xor_sync(0xffffffffu, acc[e], off);
    }
    int e0 = 0; float l0 = acc[0];
#pragma unroll
    for (int e = 1; e < EDIM; e++) if (acc[e] > l0) { l0 = acc[e]; e0 = e; }
    int e1 = -1; float l1 = -INFINITY;
#pragma unroll
    for (int e = 0; e < EDIM; e++) if (e != e0 && acc[e] > l1) { l1 = acc[e]; e1 = e; }

    float ex = expf(l1 - l0);
    float p0 = 1.f / (1.f + ex);
    float p1 = ex * p0;

    int s0 = 0, s1 = 0;
    if (lane == 0) {
        s0 = atomicAdd(&g_cnt[e0], 1);
        s1 = atomicAdd(&g_cnt[e1], 1);
        g_prob[e0 * CAP + s0] = p0;
        g_prob[e1 * CAP + s1] = p1;
        g_pidx[2 * t + 0] = e0 * CAP + s0;
        g_pidx[2 * t + 1] = e1 * CAP + s1;
    }
    s0 = __shfl_sync(0xffffffffu, s0, 0);
    s1 = __shfl_sync(0xffffffffu, s1, 0);

    __half2* d0 = reinterpret_cast<__half2*>(g_xbuf + ((size_t)e0 * CAP + s0) * CDIM);
    __half2* d1 = reinterpret_cast<__half2*>(g_xbuf + ((size_t)e1 * CAP + s1) * CDIM);
    const float2* x2 = reinterpret_cast<const float2*>(xr);
#pragma unroll
    for (int j = 0; j < CDIM / 64; j++) {
        int i = lane + 32 * j;
        float2 v = x2[i];
        __half2 h = __floats2half2_rn(v.x, v.y);
        d0[i] = h;
        d1[i] = h;
    }
}

// ======== GEMM1: fused fc+gate, block 128x64(x2), BK=64, fp16 mma, cp.async 2-stage ========
// smem halves: A[2][128*72] | Bf[2][64*72] | Bg[2][64*72]  = 36864 halves = 73728 B
#define G1_AH    9216            // halves per A stage
#define G1_BH    4608            // halves per B stage (each matrix)
#define G1_BF0H  (2 * G1_AH)
#define G1_BG0H  (G1_BF0H + 2 * G1_BH)
#define G1_SMEM_BYTES ((G1_BG0H + 2 * G1_BH) * 2)

__global__ __launch_bounds__(256, 2) void gemm1_kernel(const float* __restrict__ bfc,
                                                       const float* __restrict__ bgt) {
    extern __shared__ __half smh[];
    const int e   = blockIdx.z;
    const int cnt = g_cnt[e];
    const int m0  = blockIdx.y * 128;
    if (m0 >= cnt) return;
    const int n0  = blockIdx.x * 64;

    const __half* Ag = g_xbuf + (size_t)e * CAP * CDIM;
    const __half* B0 = g_wfcH + (size_t)e * CDIM * HDIM;
    const __half* B1 = g_wgtH + (size_t)e * CDIM * HDIM;

    const int tid = threadIdx.x, lane = tid & 31, wid = tid >> 5;
    const int wm = (wid & 3) * 32, wn = (wid >> 2) * 32;
    const int gq = lane >> 2, tg = lane & 3;
    const int grp = lane >> 3, rin = lane & 7;

    const uint32_t sBase = smem_u32(smh);

    auto load_stage = [&](int buf, int k0) {
        // A: 128 rows x 128B = 1024 chunks, 4/thread
#pragma unroll
        for (int i = 0; i < 4; i++) {
            int v = tid + 256 * i, row = v >> 3, c16 = v & 7;
            int sz = (m0 + row < cnt) ? 16 : 0;
            cpa16(sBase + (uint32_t)(buf * G1_AH + row * 72 + c16 * 8) * 2,
                  Ag + (size_t)(m0 + row) * CDIM + k0 + c16 * 8, sz);
        }
        // B each: 64 rows x 128B = 512 chunks, 2/thread per matrix
#pragma unroll
        for (int i = 0; i < 2; i++) {
            int v = tid + 256 * i, row = v >> 3, c16 = v & 7;
            size_t off = (size_t)(k0 + row) * HDIM + n0 + c16 * 8;
            cpa16u(sBase + (uint32_t)(G1_BF0H + buf * G1_BH + row * 72 + c16 * 8) * 2, B0 + off);
            cpa16u(sBase + (uint32_t)(G1_BG0H + buf * G1_BH + row * 72 + c16 * 8) * 2, B1 + off);
        }
        cpa_commit();
    };

    float cf[2][4][4] = {};
    float cg[2][4][4] = {};

    const int NIT = CDIM / 64;  // 12
    load_stage(0, 0);
    load_stage(1, 64);

#pragma unroll 1
    for (int it = 0; it < NIT; ++it) {
        const int cur = it & 1;
        if (it + 1 < NIT) cpa_wait1(); else cpa_wait0();
        __syncthreads();

        const uint32_t aB  = sBase + (uint32_t)(cur * G1_AH) * 2;
        const uint32_t bfB = sBase + (uint32_t)(G1_BF0H + cur * G1_BH) * 2;
        const uint32_t bgB = sBase + (uint32_t)(G1_BG0H + cur * G1_BH) * 2;

        unsigned uA[2][2][4], uBf[2][4][2], uBg[2][4][2];

        auto ldfrag = [&](int ks, int s) {
            const int kb = ks * 16;
#pragma unroll
            for (int mt = 0; mt < 2; mt++) {
                int r = wm + mt * 16 + (grp & 1) * 8 + rin;
                ldsm_x4(uA[s][mt], aB + (uint32_t)((r * 72 + kb + (grp >> 1) * 8) * 2));
            }
#pragma unroll
            for (int p = 0; p < 2; p++) {
                int kr = kb + (grp & 1) * 8 + rin;
                int cc = wn + p * 16 + (grp >> 1) * 8;
                unsigned r4[4];
                ldsm_x4t(r4, bfB + (uint32_t)((kr * 72 + cc) * 2));
                uBf[s][2 * p + 0][0] = r4[0]; uBf[s][2 * p + 0][1] = r4[1];
                uBf[s][2 * p + 1][0] = r4[2]; uBf[s][2 * p + 1][1] = r4[3];
                ldsm_x4t(r4, bgB + (uint32_t)((kr * 72 + cc) * 2));
                uBg[s][2 * p + 0][0] = r4[0]; uBg[s][2 * p + 0][1] = r4[1];
                uBg[s][2 * p + 1][0] = r4[2]; uBg[s][2 * p + 1][1] = r4[3];
            }
        };

        ldfrag(0, 0);
#pragma unroll
        for (int ks = 0; ks < 4; ks++) {
            const int s = ks & 1;
            if (ks < 3) ldfrag(ks + 1, s ^ 1);
#pragma unroll
            for (int mt = 0; mt < 2; mt++)
#pragma unroll
                for (int nt = 0; nt < 4; nt++) {
                    mma_f16(cf[mt][nt], uA[s][mt], uBf[s][nt]);
                    mma_f16(cg[mt][nt], uA[s][mt], uBg[s][nt]);
                }
        }
        __syncthreads();
        if (it + 2 < NIT) load_stage(cur, (it + 2) * 64);
    }

    // epilogue: u = (h+bfc) * silu(g+bg) -> fp16
    __half* U = g_u + (size_t)e * CAP * HDIM;
#pragma unroll
    for (int mt = 0; mt < 2; mt++) {
#pragma unroll
        for (int nt = 0; nt < 4; nt++) {
            int col = n0 + wn + nt * 8 + tg * 2;
            float bf0 = bfc[(size_t)e * HDIM + col], bf1 = bfc[(size_t)e * HDIM + col + 1];
            float bg0 = bgt[(size_t)e * HDIM + col], bg1 = bgt[(size_t)e * HDIM + col + 1];
            int r0 = m0 + wm + mt * 16 + gq;
            if (r0 < cnt) {
                float h0 = cf[mt][nt][0] + bf0, h1 = cf[mt][nt][1] + bf1;
                float q0 = cg[mt][nt][0] + bg0, q1 = cg[mt][nt][1] + bg1;
                float u0 = h0 * (q0 / (1.f + expf(-q0)));
                float u1 = h1 * (q1 / (1.f + expf(-q1)));
                *reinterpret_cast<__half2*>(U + (size_t)r0 * HDIM + col) = __floats2half2_rn(u0, u1);
            }
            int r1 = r0 + 8;
            if (r1 < cnt) {
                float h0 = cf[mt][nt][2] + bf0, h1 = cf[mt][nt][3] + bf1;
                float q0 = cg[mt][nt][2] + bg0, q1 = cg[mt][nt][3] + bg1;
                float u0 = h0 * (q0 / (1.f + expf(-q0)));
                float u1 = h1 * (q1 / (1.f + expf(-q1)));
                *reinterpret_cast<__half2*>(U + (size_t)r1 * HDIM + col) = __floats2half2_rn(u0, u1);
            }
        }
    }
}

// ======== GEMM2: proj, block 128x128, warp 64x32, BK=64, fp16 mma, 2-stage, split-K=3 ========
// smem halves: A[2][128*72] | B[2][64*136] = 35840 halves = 71680 B
#define G2_AH   9216
#define G2_BH   8704
#define G2_B0H  (2 * G2_AH)
#define G2_SMEM_BYTES ((G2_B0H + 2 * G2_BH) * 2)
#define NSPLIT 3
#define SPLITK (HDIM / NSPLIT)   // 1024

__global__ __launch_bounds__(256, 2) void gemm2_kernel(const float* __restrict__ bpr) {
    extern __shared__ __half smh[];
    const int e     = blockIdx.z / NSPLIT;
    const int split = blockIdx.z % NSPLIT;
    const int cnt   = g_cnt[e];
    const int m0    = blockIdx.y * 128;
    if (m0 >= cnt) return;
    const int n0    = blockIdx.x * 128;
    const int kbase = split * SPLITK;

    const __half* Ag = g_u + (size_t)e * CAP * HDIM + kbase;
    const __half* Bp = g_wprH + (size_t)e * HDIM * CDIM + (size_t)kbase * CDIM;

    const int tid = threadIdx.x, lane = tid & 31, wid = tid >> 5;
    const int wm = (wid & 1) * 64, wn = (wid >> 1) * 32;
    const int gq = lane >> 2, tg = lane & 3;
    const int grp = lane >> 3, rin = lane & 7;

    const uint32_t sBase = smem_u32(smh);

    auto load_stage = [&](int buf, int k0) {
#pragma unroll
        for (int i = 0; i < 4; i++) {
            int v = tid + 256 * i, row = v >> 3, c16 = v & 7;
            int sz = (m0 + row < cnt) ? 16 : 0;
            cpa16(sBase + (uint32_t)(buf * G2_AH + row * 72 + c16 * 8) * 2,
                  Ag + (size_t)(m0 + row) * HDIM + k0 + c16 * 8, sz);
        }
        // B: 64 rows x 256B = 1024 chunks, 4/thread
#pragma unroll
        for (int i = 0; i < 4; i++) {
            int v = tid + 256 * i, row = v >> 4, c16 = v & 15;
            cpa16u(sBase + (uint32_t)(G2_B0H + buf * G2_BH + row * 136 + c16 * 8) * 2,
                   Bp + (size_t)(k0 + row) * CDIM + n0 + c16 * 8);
        }
        cpa_commit();
    };

    float acc[4][4][4] = {};

    const int NIT = SPLITK / 64;  // 16
    load_stage(0, 0);
    load_stage(1, 64);

#pragma unroll 1
    for (int it = 0; it < NIT; ++it) {
        const int cur = it & 1;
        if (it + 1 < NIT) cpa_wait1(); else cpa_wait0();
        __syncthreads();

        const uint32_t aB = sBase + (uint32_t)(cur * G2_AH) * 2;
        const uint32_t bB = sBase + (uint32_t)(G2_B0H + cur * G2_BH) * 2;

        unsigned uA[2][4][4], uB[2][4][2];

        auto ldfrag = [&](int ks, int s) {
            const int kb = ks * 16;
#pragma unroll
            for (int mt = 0; mt < 4; mt++) {
                int r = wm + mt * 16 + (grp & 1) * 8 + rin;
                ldsm_x4(uA[s][mt], aB + (uint32_t)((r * 72 + kb + (grp >> 1) * 8) * 2));
            }
#pragma unroll
            for (int p = 0; p < 2; p++) {
                int kr = kb + (grp & 1) * 8 + rin;
                int cc = wn + p * 16 + (grp >> 1) * 8;
                unsigned r4[4];
                ldsm_x4t(r4, bB + (uint32_t)((kr * 136 + cc) * 2));
                uB[s][2 * p + 0][0] = r4[0]; uB[s][2 * p + 0][1] = r4[1];
                uB[s][2 * p + 1][0] = r4[2]; uB[s][2 * p + 1][1] = r4[3];
            }
        };

        ldfrag(0, 0);
#pragma unroll
        for (int ks = 0; ks < 4; ks++) {
            const int s = ks & 1;
            if (ks < 3) ldfrag(ks + 1, s ^ 1);
#pragma unroll
            for (int mt = 0; mt < 4; mt++)
#pragma unroll
                for (int nt = 0; nt < 4; nt++)
                    mma_f16(acc[mt][nt], uA[s][mt], uB[s][nt]);
        }
        __syncthreads();
        if (it + 2 < NIT) load_stage(cur, (it + 2) * 64);
    }

    float* O = (split == 0 ? g_o : (split == 1 ? g_o2 : g_o3)) + (size_t)e * CAP * CDIM;
#pragma unroll
    for (int mt = 0; mt < 4; mt++) {
#pragma unroll
        for (int nt = 0; nt < 4; nt++) {
            int col = n0 + wn + nt * 8 + tg * 2;
            float b0 = 0.f, b1 = 0.f;
            if (split == 0) {
                b0 = bpr[(size_t)e * CDIM + col];
                b1 = bpr[(size_t)e * CDIM + col + 1];
            }
            int r0 = m0 + wm + mt * 16 + gq;
            if (r0 < cnt) {
                float2 o; o.x = acc[mt][nt][0] + b0; o.y = acc[mt][nt][1] + b1;
                *(float2*)(O + (size_t)r0 * CDIM + col) = o;
            }
            int r1 = r0 + 8;
            if (r1 < cnt) {
                float2 o; o.x = acc[mt][nt][2] + b0; o.y = acc[mt][nt][3] + b1;
                *(float2*)(O + (size_t)r1 * CDIM + col) = o;
            }
        }
    }
}

// ---------------- kernel 4: deterministic combine (sums 3 split-K parts) ----------------
__global__ __launch_bounds__(192) void combine_kernel(float* __restrict__ out) {
    const int t = blockIdx.x;
    const int c4 = threadIdx.x;
    const int i0 = g_pidx[2 * t + 0];
    const int i1 = g_pidx[2 * t + 1];
    const float p0 = g_prob[i0];
    const float p1 = g_prob[i1];
    const float4 a0 = reinterpret_cast<const float4*>(g_o  + (size_t)i0 * CDIM)[c4];
    const float4 a1 = reinterpret_cast<const float4*>(g_o2 + (size_t)i0 * CDIM)[c4];
    const float4 a2 = reinterpret_cast<const float4*>(g_o3 + (size_t)i0 * CDIM)[c4];
    const float4 b0 = reinterpret_cast<const float4*>(g_o  + (size_t)i1 * CDIM)[c4];
    const float4 b1 = reinterpret_cast<const float4*>(g_o2 + (size_t)i1 * CDIM)[c4];
    const float4 b2 = reinterpret_cast<const float4*>(g_o3 + (size_t)i1 * CDIM)[c4];
    float4 y;
    y.x = p0 * (a0.x + a1.x + a2.x) + p1 * (b0.x + b1.x + b2.x);
    y.y = p0 * (a0.y + a1.y + a2.y) + p1 * (b0.y + b1.y + b2.y);
    y.z = p0 * (a0.z + a1.z + a2.z) + p1 * (b0.z + b1.z + b2.z);
    y.w = p0 * (a0.w + a1.w + a2.w) + p1 * (b0.w + b1.w + b2.w);
    reinterpret_cast<float4*>(out + (size_t)t * CDIM)[c4] = y;
}

// ---------------- launch ----------------
extern "C" void kernel_launch(void* const* d_in, const int* in_sizes, int n_in,
                              void* d_out, int out_size) {
    const float* x    = (const float*)d_in[0];
    const float* wr   = (const float*)d_in[1];
    const float* wfc  = (const float*)d_in[2];
    const float* bfc  = (const float*)d_in[3];
    const float* wgt  = (const float*)d_in[4];
    const float* bgt  = (const float*)d_in[5];
    const float* wpr  = (const float*)d_in[6];
    const float* bpr  = (const float*)d_in[7];
    float* out = (float*)d_out;

    // REQUIRED: dynamic smem exceeds the 48KB default opt-in
    cudaFuncSetAttribute(gemm1_kernel, cudaFuncAttributeMaxDynamicSharedMemorySize, G1_SMEM_BYTES);
    cudaFuncSetAttribute(gemm2_kernel, cudaFuncAttributeMaxDynamicSharedMemorySize, G2_SMEM_BYTES);

    __half* wfcH; cudaGetSymbolAddress((void**)&wfcH, g_wfcH);
    __half* wgtH; cudaGetSymbolAddress((void**)&wgtH, g_wgtH);
    __half* wprH; cudaGetSymbolAddress((void**)&wprH, g_wprH);

    init_kernel<<<1, 32>>>();
    convert_all_kernel<<<3 * CBLKS_PER, 256>>>((const float4*)wfc, (const float4*)wgt,
                                               (const float4*)wpr,
                                               (__half2*)wfcH, (__half2*)wgtH, (__half2*)wprH);
    router_kernel<<<NTOK / 8, 256>>>(x, wr);
    gemm1_kernel<<<dim3(HDIM / 64, CAP / 128, EDIM), 256, G1_SMEM_BYTES>>>(bfc, bgt);
    gemm2_kernel<<<dim3(CDIM / 128, CAP / 128, EDIM * NSPLIT), 256, G2_SMEM_BYTES>>>(bpr);
    combine_kernel<<<NTOK, 192>>>(out);
}